// round 11
// baseline (speedup 1.0000x reference)
#include <cuda_runtime.h>

// CNF_plain: B=131072 samples, D=8, H=128.
// dz_dt  = MLP(concat(z,t))          -> out[0 .. B*8)
// dlogp  = -trace(d(dz_dt)/dz)       -> out[B*8 .. B*9)
//
// Trace trick: trace = sum_j s2_j * sum_k s1_k * G[k,j],
//   G[k,j] = W2[k,j] * sum_d W3[j,d] * W1[d,k]  (precomputed once).
// R8 (third resubmit; broker timeouts): sample-packed f32x2 accumulators
// (h/s pairs pre-packed from broadcast LDS; 8 weight-dup movs per k instead
// of 16), branch-free MUFU tanh (ex2+rcp), f32x2 layer 3.

#define BTOT 131072
#define DD 8
#define HH 128
#define SPW 8                   // samples per warp per group
#define WARPS 8
#define NTHREADS (WARPS * 32)
#define NGROUPS (BTOT / SPW)
#define HSROW 20                // h[8] | s[8] | pad[4]  (80B, odd 16B count)
#define H2STRIDE 132            // padded stride (33 x 16B, odd) h2 + W3T rows
#define WBUF (HH * HSROW + 64)  // hs rows + z staging = 2624 floats

typedef unsigned long long u64;

// d = (a.lo*b.lo+c.lo, a.hi*b.hi+c.hi)  — packed f32x2 FMA (sm_100+)
#define FMA2(d, a, b, c) \
    asm("fma.rn.f32x2 %0, %1, %2, %3;" : "=l"(d) : "l"(a), "l"(b), "l"(c))
#define PACK2(d, x, y) \
    asm("mov.b64 %0, {%1, %2};" : "=l"(d) : "f"(x), "f"(y))
#define UNPACK2(x, y, d) \
    asm("mov.b64 {%0, %1}, %2;" : "=f"(x), "=f"(y) : "l"(d))
// 16B shared load as two packed b64 (two f32 pairs)
#define LDSV2B64(d0, d1, saddr) \
    asm("ld.shared.v2.b64 {%0, %1}, [%2];" : "=l"(d0), "=l"(d1) : "r"(saddr))

// Branch-free tanh via MUFU: u = rcp(exp(2x)+1); h = 1-2u; s = 1-h^2 = 4u(1-u)
// Correct limits: x->+inf: e=inf, u=0, h=1, s=0.  x->-inf: e=0, u=1, h=-1, s=0.
__device__ __forceinline__ float tanh_fast(float x, float& s) {
    float e, u;
    asm("ex2.approx.ftz.f32 %0, %1;" : "=f"(e) : "f"(x * 2.885390081777927f));
    asm("rcp.approx.ftz.f32 %0, %1;" : "=f"(u) : "f"(e + 1.0f));
    s = 4.0f * u * (1.0f - u);
    return fmaf(-2.0f, u, 1.0f);
}

__device__ float g_G[HH * HH];

__global__ void precompute_G_kernel(const float* __restrict__ W1,
                                    const float* __restrict__ W2,
                                    const float* __restrict__ W3) {
    int j = threadIdx.x;   // 0..127
    int k = blockIdx.x;    // 0..127
    float m = 0.0f;
#pragma unroll
    for (int d = 0; d < DD; ++d)
        m = fmaf(W3[j * DD + d], W1[d * HH + k], m);
    g_G[k * HH + j] = W2[k * HH + j] * m;
}

__global__ __launch_bounds__(NTHREADS, 1)
void cnf_kernel(const float* __restrict__ z,
                const float* __restrict__ tptr,
                const float* __restrict__ W1,
                const float* __restrict__ b1,
                const float* __restrict__ W2,
                const float* __restrict__ b2,
                const float* __restrict__ W3,
                const float* __restrict__ b3,
                float* __restrict__ out) {
    extern __shared__ float smem[];
    float* sW2   = smem;                       // 16384 floats
    float* sG    = sW2 + HH * HH;              // 16384
    float* sW1   = sG + HH * HH;               // 1152
    float* sb1   = sW1 + (DD + 1) * HH;        // 128
    float* sb2   = sb1 + HH;                   // 128
    float* sW3T  = sb2 + HH;                   // 8 x 132 (transposed, padded)
    float* sb3   = sW3T + DD * H2STRIDE;       // 8
    float* wbase = sb3 + 8;                    // WARPS * WBUF (16B-aligned)

    for (int i = threadIdx.x; i < HH * HH; i += NTHREADS) {
        sW2[i] = W2[i];
        sG[i]  = g_G[i];
    }
    for (int i = threadIdx.x; i < (DD + 1) * HH; i += NTHREADS) sW1[i] = W1[i];
    if (threadIdx.x < HH) {
        sb1[threadIdx.x] = b1[threadIdx.x];
        sb2[threadIdx.x] = b2[threadIdx.x];
    }
    for (int i = threadIdx.x; i < HH * DD; i += NTHREADS) {
        int j = i >> 3, d = i & 7;
        sW3T[d * H2STRIDE + j] = W3[i];        // transpose
    }
    if (threadIdx.x < DD) sb3[threadIdx.x] = b3[threadIdx.x];
    __syncthreads();

    const float t = tptr[0];
    const int warp = threadIdx.x >> 5;
    const int lane = threadIdx.x & 31;
    float* hsw = wbase + warp * WBUF;  // [k][HSROW]: h 0..7, s 8..15; h2 reuse
    float* zw  = hsw + HH * HSROW;     // z staging: [s][d], 64 floats

    const unsigned w_base =
        (unsigned)__cvta_generic_to_shared(sW2) + (unsigned)(16 * lane);
    const unsigned g_base =
        (unsigned)__cvta_generic_to_shared(sG) + (unsigned)(16 * lane);
    const unsigned hs_base = (unsigned)__cvta_generic_to_shared(hsw);
    const unsigned w3_base = (unsigned)__cvta_generic_to_shared(sW3T);

    float* logp_out = out + (size_t)BTOT * DD;

    const int gstride = gridDim.x * WARPS;
    int g = blockIdx.x * WARPS + warp;

    // Prefetch first group's z (64 consecutive floats per warp, coalesced)
    float zr0 = 0.0f, zr1 = 0.0f;
    if (g < NGROUPS) {
        zr0 = z[(size_t)g * 64 + lane];
        zr1 = z[(size_t)g * 64 + lane + 32];
    }

    for (; g < NGROUPS; g += gstride) {
        const int s0 = g * SPW;

        // Stage this group's z; prefetch next group's to hide LDG latency.
        zw[lane]      = zr0;
        zw[lane + 32] = zr1;
        __syncwarp();
        {
            const int gn = g + gstride;
            if (gn < NGROUPS) {
                zr0 = z[(size_t)gn * 64 + lane];
                zr1 = z[(size_t)gn * 64 + lane + 32];
            }
        }

        // ---- Layer 1: lane handles k = lane + 32*i; W1 column in registers ----
#pragma unroll
        for (int i = 0; i < 4; ++i) {
            const int k = lane + 32 * i;
            float w1r[DD];
#pragma unroll
            for (int d = 0; d < DD; ++d) w1r[d] = sW1[d * HH + k];
            const float base0 = fmaf(t, sW1[8 * HH + k], sb1[k]);
            float hv[SPW], sv[SPW];
#pragma unroll
            for (int s = 0; s < SPW; ++s) {
                const float4 za = *(const float4*)&zw[s * DD];
                const float4 zb = *(const float4*)&zw[s * DD + 4];
                float a = base0;
                a = fmaf(za.x, w1r[0], a); a = fmaf(za.y, w1r[1], a);
                a = fmaf(za.z, w1r[2], a); a = fmaf(za.w, w1r[3], a);
                a = fmaf(zb.x, w1r[4], a); a = fmaf(zb.y, w1r[5], a);
                a = fmaf(zb.z, w1r[6], a); a = fmaf(zb.w, w1r[7], a);
                hv[s] = tanh_fast(a, sv[s]);
            }
            float* row = hsw + k * HSROW;   // 80B lane stride: conflict-free
            *(float4*)&row[0]  = make_float4(hv[0], hv[1], hv[2], hv[3]);
            *(float4*)&row[4]  = make_float4(hv[4], hv[5], hv[6], hv[7]);
            *(float4*)&row[8]  = make_float4(sv[0], sv[1], sv[2], sv[3]);
            *(float4*)&row[12] = make_float4(sv[4], sv[5], sv[6], sv[7]);
        }
        __syncwarp();

        // ---- Layer 2 (a2 = h1@W2+b2) fused with trace matvec (v = s1@G).
        // Sample-packed f32x2: acc2[sp][j] holds samples (2sp,2sp+1) for
        // output j = 4*lane+j. h/s pairs arrive pre-packed from broadcast
        // v2.b64 loads; only the 4+4 weights per k need duplication movs.
        u64 acc2[4][4], vac2[4][4];
        {
            u64 bp01, bp23;
            const unsigned b2a =
                (unsigned)__cvta_generic_to_shared(sb2) + (unsigned)(16 * lane);
            LDSV2B64(bp01, bp23, b2a);
            float b0, b1v, b2v, b3v;
            UNPACK2(b0, b1v, bp01); UNPACK2(b2v, b3v, bp23);
            u64 bd[4];
            PACK2(bd[0], b0, b0);   PACK2(bd[1], b1v, b1v);
            PACK2(bd[2], b2v, b2v); PACK2(bd[3], b3v, b3v);
#pragma unroll
            for (int sp = 0; sp < 4; ++sp)
#pragma unroll
                for (int j = 0; j < 4; ++j) {
                    acc2[sp][j] = bd[j];
                    vac2[sp][j] = 0ull;
                }
        }
#pragma unroll 2
        for (int k = 0; k < HH; ++k) {
            const unsigned rowa = hs_base + (unsigned)(k * (HSROW * 4));
            u64 hp[4], sp_[4];
            LDSV2B64(hp[0], hp[1], rowa);        // (h0,h1),(h2,h3) broadcast
            LDSV2B64(hp[2], hp[3], rowa + 16);   // (h4,h5),(h6,h7)
            LDSV2B64(sp_[0], sp_[1], rowa + 32);
            LDSV2B64(sp_[2], sp_[3], rowa + 48);
            u64 wp01, wp23, gp01, gp23;
            LDSV2B64(wp01, wp23, w_base + (unsigned)(k * (HH * 4)));
            LDSV2B64(gp01, gp23, g_base + (unsigned)(k * (HH * 4)));
            float w0, w1v, w2v, w3v, g0, g1v, g2v, g3v;
            UNPACK2(w0, w1v, wp01);  UNPACK2(w2v, w3v, wp23);
            UNPACK2(g0, g1v, gp01);  UNPACK2(g2v, g3v, gp23);
            u64 wd[4], gd[4];
            PACK2(wd[0], w0, w0);    PACK2(wd[1], w1v, w1v);
            PACK2(wd[2], w2v, w2v);  PACK2(wd[3], w3v, w3v);
            PACK2(gd[0], g0, g0);    PACK2(gd[1], g1v, g1v);
            PACK2(gd[2], g2v, g2v);  PACK2(gd[3], g3v, g3v);
#pragma unroll
            for (int sp = 0; sp < 4; ++sp)
#pragma unroll
                for (int j = 0; j < 4; ++j) {
                    FMA2(acc2[sp][j], hp[sp], wd[j], acc2[sp][j]);
                    FMA2(vac2[sp][j], sp_[sp], gd[j], vac2[sp][j]);
                }
        }
        __syncwarp();  // all lanes done reading hs rows before h2 reuse

        // ---- tanh + trace partials; store h2 [s][j] with padded stride ----
        float tpart[SPW];
#pragma unroll
        for (int sp = 0; sp < 4; ++sp) {
            float aL[4], aH[4], vL[4], vH[4];
#pragma unroll
            for (int j = 0; j < 4; ++j) {
                UNPACK2(aL[j], aH[j], acc2[sp][j]);
                UNPACK2(vL[j], vH[j], vac2[sp][j]);
            }
            float hL[4], hH[4], tpL = 0.0f, tpH = 0.0f;
#pragma unroll
            for (int j = 0; j < 4; ++j) {
                float s2L, s2H;
                hL[j] = tanh_fast(aL[j], s2L);
                hH[j] = tanh_fast(aH[j], s2H);
                tpL = fmaf(vL[j], s2L, tpL);
                tpH = fmaf(vH[j], s2H, tpH);
            }
            tpart[2 * sp]     = tpL;
            tpart[2 * sp + 1] = tpH;
            *(float4*)&hsw[(2 * sp) * H2STRIDE + 4 * lane] =
                make_float4(hL[0], hL[1], hL[2], hL[3]);
            *(float4*)&hsw[(2 * sp + 1) * H2STRIDE + 4 * lane] =
                make_float4(hH[0], hH[1], hH[2], hH[3]);
        }
        __syncwarp();

        // ---- Trace: butterfly-reduce partials across warp ----
#pragma unroll
        for (int off = 16; off; off >>= 1) {
#pragma unroll
            for (int s = 0; s < SPW; ++s)
                tpart[s] += __shfl_xor_sync(0xffffffffu, tpart[s], off);
        }
        if (lane == 0) {
#pragma unroll
            for (int s = 0; s < SPW; ++s) logp_out[s0 + s] = -tpart[s];
        }

        // ---- dz/dt: 64 items = (8 samples x 8 dims); f32x2 dots ----
        {
            const int d = lane & 7;
            const unsigned w3a = w3_base + (unsigned)(d * (H2STRIDE * 4));
#pragma unroll
            for (int i = 0; i < 2; ++i) {
                const int s = (lane >> 3) + 4 * i;
                const unsigned h2a = hs_base + (unsigned)(s * (H2STRIDE * 4));
                u64 o2;
                PACK2(o2, sb3[d], 0.0f);
#pragma unroll 8
                for (int j = 0; j < HH; j += 4) {
                    u64 hA, hB, wA, wB;
                    LDSV2B64(hA, hB, h2a + (unsigned)(j * 4));
                    LDSV2B64(wA, wB, w3a + (unsigned)(j * 4));
                    FMA2(o2, hA, wA, o2);
                    FMA2(o2, hB, wB, o2);
                }
                float oL, oH;
                UNPACK2(oL, oH, o2);
                out[(size_t)(s0 + s) * DD + d] = oL + oH;  // coalesced 128B
            }
        }
        __syncwarp();  // h2 reads done before next iter's layer-1 stores
    }
}

extern "C" void kernel_launch(void* const* d_in, const int* in_sizes, int n_in,
                              void* d_out, int out_size) {
    const float* z  = (const float*)d_in[0];
    // d_in[1] = logp_z (unused by the math)
    const float* t  = (const float*)d_in[2];
    const float* W1 = (const float*)d_in[3];
    const float* b1 = (const float*)d_in[4];
    const float* W2 = (const float*)d_in[5];
    const float* b2 = (const float*)d_in[6];
    const float* W3 = (const float*)d_in[7];
    const float* b3 = (const float*)d_in[8];
    float* out = (float*)d_out;

    precompute_G_kernel<<<HH, HH>>>(W1, W2, W3);

    const int smem_bytes =
        (2 * HH * HH + (DD + 1) * HH + HH + HH + DD * H2STRIDE + 8 +
         WARPS * WBUF) * (int)sizeof(float);  // ~219.7 KB < 227 KB cap
    cudaFuncSetAttribute(cnf_kernel,
                         cudaFuncAttributeMaxDynamicSharedMemorySize, smem_bytes);

    int nsm = 148;
    cudaDeviceGetAttribute(&nsm, cudaDevAttrMultiProcessorCount, 0);

    cnf_kernel<<<nsm, NTHREADS, smem_bytes>>>(z, t, W1, b1, W2, b2, W3, b3, out);
}